// round 4
// baseline (speedup 1.0000x reference)
#include <cuda_runtime.h>
#include <cuda_bf16.h>
#include <math.h>

// Problem constants
#define B_   32
#define H_   32
#define KV_  8
#define G_   4      // H/KV
#define S_   4096
#define D_   64
#define HID_ 2048
#define FF_  8192
#define V_   32000
#define NSPLIT 16
#define SC_  (S_/NSPLIT)   // 256

// ---------------- scratch (device global; no allocation allowed) -------------
// ctx 65536 | h1 65536 | x2 65536 | ff 262144 | h3 65536 | xf 65536
// opart 32*8*4*16*64 = 1048576 | ml 32768 | part 524288
#define OFF_CTX   0
#define OFF_H1    (OFF_CTX + B_*HID_)
#define OFF_X2    (OFF_H1 + B_*HID_)
#define OFF_FF    (OFF_X2 + B_*HID_)
#define OFF_H3    (OFF_FF + B_*FF_)
#define OFF_XF    (OFF_H3 + B_*HID_)
#define OFF_OPART (OFF_XF + B_*HID_)
#define OFF_ML    (OFF_OPART + B_*KV_*G_*NSPLIT*D_)
#define OFF_PART  (OFF_ML + B_*KV_*G_*NSPLIT*2)
#define SCRATCH_TOTAL (OFF_PART + 8*B_*FF_)   // 8-way K-split x 32 x max-N(8192)

__device__ float g_scratch[SCRATCH_TOTAL];

// packed f32x2 FMA: d(lo,hi) += a(lo,hi)*b(lo,hi). sm_103a-only PTX.
__device__ __forceinline__ void ffma2(unsigned long long &d,
                                      unsigned long long a,
                                      unsigned long long b) {
    asm("fma.rn.f32x2 %0, %1, %2, %0;" : "+l"(d) : "l"(a), "l"(b));
}

// =============================================================================
// Kernel 1: flash-decode attention partials.
// grid (NSPLIT, KV, B), 256 threads. Each block: one S-chunk of 256, G=4 heads.
// =============================================================================
__global__ __launch_bounds__(256)
void attn_partial(const float* __restrict__ q, const float* __restrict__ ks,
                  const float* __restrict__ vs,
                  float* __restrict__ opart, float* __restrict__ ml) {
    const int split = blockIdx.x, kv = blockIdx.y, b = blockIdx.z;
    const int tid = threadIdx.x;

    __shared__ float4 qs4[G_][16];          // q for 4 heads, as float4
    __shared__ float  sc[G_][SC_];          // scores -> probabilities
    __shared__ float  red[256];
    __shared__ float  ms[G_], ls[G_];
    __shared__ float4 pc[4][G_][16];        // partial ctx from 4 s-groups

    // load q (4 heads x 64)
    {
        int g = tid >> 6, kk = tid & 63;
        reinterpret_cast<float*>(qs4)[tid] =
            q[((size_t)b * H_ + kv * G_ + g) * D_ + kk];
    }
    __syncthreads();

    const int s0 = split * SC_;
    // ---- pass 1: scores. thread = one s position.
    {
        const float4* kp = reinterpret_cast<const float4*>(
            ks + (((size_t)b * KV_ + kv) * S_ + s0 + tid) * D_);
        float d0 = 0.f, d1 = 0.f, d2 = 0.f, d3 = 0.f;
#pragma unroll
        for (int k4 = 0; k4 < 16; k4++) {
            float4 kvv = kp[k4];
            float4 q0 = qs4[0][k4], q1 = qs4[1][k4];
            float4 q2 = qs4[2][k4], q3 = qs4[3][k4];
            d0 += kvv.x*q0.x + kvv.y*q0.y + kvv.z*q0.z + kvv.w*q0.w;
            d1 += kvv.x*q1.x + kvv.y*q1.y + kvv.z*q1.z + kvv.w*q1.w;
            d2 += kvv.x*q2.x + kvv.y*q2.y + kvv.z*q2.z + kvv.w*q2.w;
            d3 += kvv.x*q3.x + kvv.y*q3.y + kvv.z*q3.z + kvv.w*q3.w;
        }
        const float scale = 0.125f;  // 1/sqrt(64)
        sc[0][tid] = d0 * scale; sc[1][tid] = d1 * scale;
        sc[2][tid] = d2 * scale; sc[3][tid] = d3 * scale;
    }
    __syncthreads();

    // ---- softmax stats per head (64 threads per head)
    {
        int g = tid >> 6, i = tid & 63;
        float m = -1e30f;
        for (int s = i; s < SC_; s += 64) m = fmaxf(m, sc[g][s]);
        red[tid] = m; __syncthreads();
        for (int off = 32; off > 0; off >>= 1) {
            if (i < off) red[tid] = fmaxf(red[tid], red[tid + off]);
            __syncthreads();
        }
        if (i == 0) ms[g] = red[tid];
        __syncthreads();
        float mg = ms[g];
        float l = 0.f;
        for (int s = i; s < SC_; s += 64) {
            float p = __expf(sc[g][s] - mg);
            sc[g][s] = p;
            l += p;
        }
        red[tid] = l; __syncthreads();
        for (int off = 32; off > 0; off >>= 1) {
            if (i < off) red[tid] += red[tid + off];
            __syncthreads();
        }
        if (i == 0) ls[g] = red[tid];
    }
    __syncthreads();

    // ---- pass 2: ctx = sum p*v. thread = (sgrp, g, d4)
    {
        int sg = tid >> 6, g = (tid >> 4) & 3, d4 = tid & 15;
        const float4* vp = reinterpret_cast<const float4*>(
            vs + (((size_t)b * KV_ + kv) * S_ + s0) * D_);
        float4 acc = make_float4(0.f, 0.f, 0.f, 0.f);
        for (int s = sg; s < SC_; s += 4) {
            float p = sc[g][s];
            float4 v4 = vp[s * 16 + d4];
            acc.x += p * v4.x; acc.y += p * v4.y;
            acc.z += p * v4.z; acc.w += p * v4.w;
        }
        pc[sg][g][d4] = acc;
    }
    __syncthreads();

    if (tid < 64) {
        int g = tid >> 4, d4 = tid & 15;
        float4 a = pc[0][g][d4], c1 = pc[1][g][d4];
        float4 c2 = pc[2][g][d4], c3 = pc[3][g][d4];
        float4 o;
        o.x = a.x + c1.x + c2.x + c3.x;
        o.y = a.y + c1.y + c2.y + c3.y;
        o.z = a.z + c1.z + c2.z + c3.z;
        o.w = a.w + c1.w + c2.w + c3.w;
        size_t base = ((((size_t)b * KV_ + kv) * G_ + g) * NSPLIT + split) * (size_t)D_;
        reinterpret_cast<float4*>(opart + base)[d4] = o;
    }
    if (tid < G_) {
        size_t idx = (((size_t)b * KV_ + kv) * G_ + tid) * NSPLIT + split;
        ml[idx * 2]     = ms[tid];
        ml[idx * 2 + 1] = ls[tid];
    }
}

// =============================================================================
// Kernel 2: combine split partials -> ctx [B, H*D]
// grid (G, KV, B), 64 threads
// =============================================================================
__global__ __launch_bounds__(64)
void attn_combine(const float* __restrict__ opart, const float* __restrict__ ml,
                  float* __restrict__ ctx) {
    int g = blockIdx.x, kv = blockIdx.y, b = blockIdx.z, d = threadIdx.x;
    size_t base = (((size_t)b * KV_ + kv) * G_ + g) * NSPLIT;
    float M = -1e30f;
#pragma unroll
    for (int i = 0; i < NSPLIT; i++) M = fmaxf(M, ml[(base + i) * 2]);
    float L = 0.f, acc = 0.f;
#pragma unroll
    for (int i = 0; i < NSPLIT; i++) {
        float w = __expf(ml[(base + i) * 2] - M);
        L   += ml[(base + i) * 2 + 1] * w;
        acc += opart[(base + i) * D_ + d] * w;
    }
    int h = kv * G_ + g;
    ctx[(size_t)b * HID_ + h * D_ + d] = acc / L;
}

// =============================================================================
// Batch GEMM: out[b,n] = sum_k X[b,k]*W[n,k]  (+ epilogue per MODE)
// MODE 0: + bias + resid   MODE 1: gelu(.+bias)   MODE 2: plain
// MODE 3: raw K-split partial -> out[(yc*32+b)*N + n]
// grid (N/64, KSPLIT), 256 threads. BLK_N=64, TK=64, packed f32x2 FMA.
// =============================================================================
template <int MODE>
__global__ __launch_bounds__(256)
void gemm_bn(const float* __restrict__ X, const float* __restrict__ W,
             const float* __restrict__ bias, const float* __restrict__ resid,
             float* __restrict__ out, int K, int N, int Kc) {
    __shared__ float4 wsv[64 * 16];   // [n][k4]
    __shared__ float4 xs4[16 * 32];   // [k4][b]

    const int tid = threadIdx.x;
    const int b = tid & 31, w = tid >> 5;
    const int nblk = blockIdx.x * 64;
    const int kbeg = blockIdx.y * Kc, kend = kbeg + Kc;

    unsigned long long accA[8], accB[8];
#pragma unroll
    for (int j = 0; j < 8; j++) { accA[j] = 0ull; accB[j] = 0ull; }

    for (int k0 = kbeg; k0 < kend; k0 += 64) {
#pragma unroll
        for (int r = 0; r < 4; r++) {
            int idx = tid + r * 256;
            int n = idx >> 4, k4 = idx & 15;
            wsv[idx] = *reinterpret_cast<const float4*>(
                W + (size_t)(nblk + n) * K + k0 + k4 * 4);
        }
#pragma unroll
        for (int r = 0; r < 2; r++) {
            int idx = tid + r * 256;
            int bb = idx & 31, k4 = idx >> 5;
            xs4[k4 * 32 + bb] = *reinterpret_cast<const float4*>(
                X + (size_t)bb * K + k0 + k4 * 4);
        }
        __syncthreads();

        const ulonglong2* wsp = reinterpret_cast<const ulonglong2*>(wsv);
        const ulonglong2* xsp = reinterpret_cast<const ulonglong2*>(xs4);
#pragma unroll
        for (int k4 = 0; k4 < 16; k4++) {
            ulonglong2 xv = xsp[k4 * 32 + b];
#pragma unroll
            for (int j = 0; j < 8; j++) {
                ulonglong2 wv = wsp[(w * 8 + j) * 16 + k4];
                ffma2(accA[j], xv.x, wv.x);
                ffma2(accB[j], xv.y, wv.y);
            }
        }
        __syncthreads();
    }

#pragma unroll
    for (int j = 0; j < 8; j++) {
        float2 fa = *reinterpret_cast<float2*>(&accA[j]);
        float2 fb = *reinterpret_cast<float2*>(&accB[j]);
        float val = (fa.x + fa.y) + (fb.x + fb.y);
        int n = nblk + w * 8 + j;
        if (MODE == 0) {
            val = val + bias[n] + resid[(size_t)b * N + n];
            out[(size_t)b * N + n] = val;
        } else if (MODE == 1) {
            float v = val + bias[n];
            out[(size_t)b * N + n] = 0.5f * v * (1.0f + erff(v * 0.70710678118654752f));
        } else if (MODE == 2) {
            out[(size_t)b * N + n] = val;
        } else {  // MODE 3: raw partial
            out[((size_t)blockIdx.y * B_ + b) * N + n] = val;
        }
    }
}

// Epilogue for K-split GEMMs: sum KS partials + bias/resid/act.
template <int MODE>
__global__ __launch_bounds__(256)
void epi_kernel(const float* __restrict__ part, const float* __restrict__ bias,
                const float* __restrict__ resid, float* __restrict__ out,
                int N, int KS) {
    size_t i = (size_t)blockIdx.x * 256 + threadIdx.x;
    int b = (int)(i / N);
    int n = (int)(i % N);
    float val = 0.f;
    for (int ksp = 0; ksp < KS; ksp++)
        val += part[((size_t)ksp * B_ + b) * N + n];
    if (MODE == 0) {
        val = val + bias[n] + resid[i];
    } else if (MODE == 1) {
        float v = val + bias[n];
        val = 0.5f * v * (1.0f + erff(v * 0.70710678118654752f));
    }
    out[i] = val;
}

// =============================================================================
// LayerNorm: grid B, 256 threads, row length 2048.
// =============================================================================
__global__ __launch_bounds__(256)
void ln_kernel(const float* __restrict__ in, const float* __restrict__ gg,
               const float* __restrict__ bb, float* __restrict__ out) {
    int b = blockIdx.x, tid = threadIdx.x;
    __shared__ float red[256];
    const float* row = in + (size_t)b * HID_;
    float v[8];
    float s = 0.f;
#pragma unroll
    for (int i = 0; i < 8; i++) { v[i] = row[tid + i * 256]; s += v[i]; }
    red[tid] = s; __syncthreads();
    for (int off = 128; off > 0; off >>= 1) {
        if (tid < off) red[tid] += red[tid + off];
        __syncthreads();
    }
    float mean = red[0] * (1.0f / HID_);
    __syncthreads();
    float sq = 0.f;
#pragma unroll
    for (int i = 0; i < 8; i++) { float d = v[i] - mean; sq += d * d; }
    red[tid] = sq; __syncthreads();
    for (int off = 128; off > 0; off >>= 1) {
        if (tid < off) red[tid] += red[tid + off];
        __syncthreads();
    }
    float rstd = rsqrtf(red[0] * (1.0f / HID_) + 1e-5f);
#pragma unroll
    for (int i = 0; i < 8; i++) {
        int c = tid + i * 256;
        out[(size_t)b * HID_ + c] = (v[i] - mean) * rstd * gg[c] + bb[c];
    }
}

// =============================================================================
extern "C" void kernel_launch(void* const* d_in, const int* in_sizes, int n_in,
                              void* d_out, int out_size) {
    const float* residual = (const float*)d_in[0];
    const float* q   = (const float*)d_in[1];
    const float* ks  = (const float*)d_in[2];
    const float* vs  = (const float*)d_in[3];
    const float* Wo  = (const float*)d_in[4];
    const float* bo  = (const float*)d_in[5];
    const float* g2  = (const float*)d_in[6];
    const float* b2  = (const float*)d_in[7];
    const float* W1  = (const float*)d_in[8];
    const float* b1  = (const float*)d_in[9];
    const float* W2  = (const float*)d_in[10];
    const float* b2m = (const float*)d_in[11];
    const float* gf  = (const float*)d_in[12];
    const float* bf  = (const float*)d_in[13];
    const float* Wlm = (const float*)d_in[14];
    float* out = (float*)d_out;

    float* scratch = nullptr;
    cudaGetSymbolAddress((void**)&scratch, g_scratch);
    float* ctx   = scratch + OFF_CTX;
    float* h1    = scratch + OFF_H1;
    float* x2    = scratch + OFF_X2;
    float* ff    = scratch + OFF_FF;
    float* h3    = scratch + OFF_H3;
    float* xf    = scratch + OFF_XF;
    float* opart = scratch + OFF_OPART;
    float* ml    = scratch + OFF_ML;
    float* part  = scratch + OFF_PART;

    // 1) attention
    attn_partial<<<dim3(NSPLIT, KV_, B_), 256>>>(q, ks, vs, opart, ml);
    attn_combine<<<dim3(G_, KV_, B_), 64>>>(opart, ml, ctx);

    // 2) Wo projection (+bo, +residual): K-split 8 for parallelism
    gemm_bn<3><<<dim3(HID_ / 64, 8), 256>>>(ctx, Wo, nullptr, nullptr, part,
                                            HID_, HID_, HID_ / 8);
    epi_kernel<0><<<(B_ * HID_) / 256, 256>>>(part, bo, residual, h1, HID_, 8);

    // 3) LN
    ln_kernel<<<B_, 256>>>(h1, g2, b2, x2);

    // 4) FFN up + GELU: K-split 2
    gemm_bn<3><<<dim3(FF_ / 64, 2), 256>>>(x2, W1, nullptr, nullptr, part,
                                           HID_, FF_, HID_ / 2);
    epi_kernel<1><<<(B_ * FF_) / 256, 256>>>(part, b1, nullptr, ff, FF_, 2);

    // 5) FFN down (+b2m, +h1 residual): K-split 8
    gemm_bn<3><<<dim3(HID_ / 64, 8), 256>>>(ff, W2, nullptr, nullptr, part,
                                            FF_, HID_, FF_ / 8);
    epi_kernel<0><<<(B_ * HID_) / 256, 256>>>(part, b2m, h1, h3, HID_, 8);

    // 6) final LN
    ln_kernel<<<B_, 256>>>(h3, gf, bf, xf);

    // 7) LM head -> logits (direct, 500 blocks)
    gemm_bn<2><<<dim3(V_ / 64, 1), 256>>>(xf, Wlm, nullptr, nullptr, out,
                                          HID_, V_, HID_);
}

// round 5
// speedup vs baseline: 1.0732x; 1.0732x over previous
#include <cuda_runtime.h>
#include <cuda_bf16.h>
#include <math.h>

// Problem constants
#define B_   32
#define H_   32
#define KV_  8
#define G_   4      // H/KV
#define S_   4096
#define D_   64
#define HID_ 2048
#define FF_  8192
#define V_   32000
#define NSPLIT 16
#define SC_  (S_/NSPLIT)   // 256

// ---------------- scratch (device global; no allocation allowed) -------------
#define OFF_CTX   0
#define OFF_H1    (OFF_CTX + B_*HID_)
#define OFF_X2    (OFF_H1 + B_*HID_)
#define OFF_FF    (OFF_X2 + B_*HID_)
#define OFF_H3    (OFF_FF + B_*FF_)
#define OFF_XF    (OFF_H3 + B_*HID_)
#define OFF_OPART (OFF_XF + B_*HID_)
#define OFF_ML    (OFF_OPART + B_*KV_*G_*NSPLIT*D_)
#define OFF_PART  (OFF_ML + B_*KV_*G_*NSPLIT*2)
#define SCRATCH_TOTAL (OFF_PART + 8*B_*FF_)   // 2M floats for K-split partials

__device__ float g_scratch[SCRATCH_TOTAL];

// packed f32x2 FMA: d(lo,hi) += a(lo,hi)*b(lo,hi). sm_103a-only PTX.
__device__ __forceinline__ void ffma2(unsigned long long &d,
                                      unsigned long long a,
                                      unsigned long long b) {
    asm("fma.rn.f32x2 %0, %1, %2, %0;" : "+l"(d) : "l"(a), "l"(b));
}

// =============================================================================
// Kernel 1: flash-decode attention partials.
// grid (NSPLIT, KV, B), 256 threads. Each block: one S-chunk of 256, G=4 heads.
// =============================================================================
__global__ __launch_bounds__(256)
void attn_partial(const float* __restrict__ q, const float* __restrict__ ks,
                  const float* __restrict__ vs,
                  float* __restrict__ opart, float* __restrict__ ml) {
    const int split = blockIdx.x, kv = blockIdx.y, b = blockIdx.z;
    const int tid = threadIdx.x;

    __shared__ float4 qs4[G_][16];          // q for 4 heads, as float4
    __shared__ float  sc[G_][SC_];          // scores -> probabilities
    __shared__ float  red[256];
    __shared__ float  ms[G_], ls[G_];
    __shared__ float4 pc[4][G_][16];        // partial ctx from 4 s-groups

    // load q (4 heads x 64)
    {
        int g = tid >> 6, kk = tid & 63;
        reinterpret_cast<float*>(qs4)[tid] =
            q[((size_t)b * H_ + kv * G_ + g) * D_ + kk];
    }
    __syncthreads();

    const int s0 = split * SC_;
    // ---- pass 1: scores. thread = one s position.
    {
        const float4* kp = reinterpret_cast<const float4*>(
            ks + (((size_t)b * KV_ + kv) * S_ + s0 + tid) * D_);
        float d0 = 0.f, d1 = 0.f, d2 = 0.f, d3 = 0.f;
#pragma unroll
        for (int k4 = 0; k4 < 16; k4++) {
            float4 kvv = kp[k4];
            float4 q0 = qs4[0][k4], q1 = qs4[1][k4];
            float4 q2 = qs4[2][k4], q3 = qs4[3][k4];
            d0 += kvv.x*q0.x + kvv.y*q0.y + kvv.z*q0.z + kvv.w*q0.w;
            d1 += kvv.x*q1.x + kvv.y*q1.y + kvv.z*q1.z + kvv.w*q1.w;
            d2 += kvv.x*q2.x + kvv.y*q2.y + kvv.z*q2.z + kvv.w*q2.w;
            d3 += kvv.x*q3.x + kvv.y*q3.y + kvv.z*q3.z + kvv.w*q3.w;
        }
        const float scale = 0.125f;  // 1/sqrt(64)
        sc[0][tid] = d0 * scale; sc[1][tid] = d1 * scale;
        sc[2][tid] = d2 * scale; sc[3][tid] = d3 * scale;
    }
    __syncthreads();

    // ---- softmax stats per head (64 threads per head)
    {
        int g = tid >> 6, i = tid & 63;
        float m = -1e30f;
        for (int s = i; s < SC_; s += 64) m = fmaxf(m, sc[g][s]);
        red[tid] = m; __syncthreads();
        for (int off = 32; off > 0; off >>= 1) {
            if (i < off) red[tid] = fmaxf(red[tid], red[tid + off]);
            __syncthreads();
        }
        if (i == 0) ms[g] = red[tid];
        __syncthreads();
        float mg = ms[g];
        float l = 0.f;
        for (int s = i; s < SC_; s += 64) {
            float p = __expf(sc[g][s] - mg);
            sc[g][s] = p;
            l += p;
        }
        red[tid] = l; __syncthreads();
        for (int off = 32; off > 0; off >>= 1) {
            if (i < off) red[tid] += red[tid + off];
            __syncthreads();
        }
        if (i == 0) ls[g] = red[tid];
    }
    __syncthreads();

    // ---- pass 2: ctx = sum p*v. thread = (sgrp, g, d4)
    {
        int sg = tid >> 6, g = (tid >> 4) & 3, d4 = tid & 15;
        const float4* vp = reinterpret_cast<const float4*>(
            vs + (((size_t)b * KV_ + kv) * S_ + s0) * D_);
        float4 acc = make_float4(0.f, 0.f, 0.f, 0.f);
        for (int s = sg; s < SC_; s += 4) {
            float p = sc[g][s];
            float4 v4 = vp[s * 16 + d4];
            acc.x += p * v4.x; acc.y += p * v4.y;
            acc.z += p * v4.z; acc.w += p * v4.w;
        }
        pc[sg][g][d4] = acc;
    }
    __syncthreads();

    if (tid < 64) {
        int g = tid >> 4, d4 = tid & 15;
        float4 a = pc[0][g][d4], c1 = pc[1][g][d4];
        float4 c2 = pc[2][g][d4], c3 = pc[3][g][d4];
        float4 o;
        o.x = a.x + c1.x + c2.x + c3.x;
        o.y = a.y + c1.y + c2.y + c3.y;
        o.z = a.z + c1.z + c2.z + c3.z;
        o.w = a.w + c1.w + c2.w + c3.w;
        size_t base = ((((size_t)b * KV_ + kv) * G_ + g) * NSPLIT + split) * (size_t)D_;
        reinterpret_cast<float4*>(opart + base)[d4] = o;
    }
    if (tid < G_) {
        size_t idx = (((size_t)b * KV_ + kv) * G_ + tid) * NSPLIT + split;
        ml[idx * 2]     = ms[tid];
        ml[idx * 2 + 1] = ls[tid];
    }
}

// =============================================================================
// Kernel 2: combine split partials -> ctx [B, H*D]
// =============================================================================
__global__ __launch_bounds__(64)
void attn_combine(const float* __restrict__ opart, const float* __restrict__ ml,
                  float* __restrict__ ctx) {
    int g = blockIdx.x, kv = blockIdx.y, b = blockIdx.z, d = threadIdx.x;
    size_t base = (((size_t)b * KV_ + kv) * G_ + g) * NSPLIT;
    float M = -1e30f;
#pragma unroll
    for (int i = 0; i < NSPLIT; i++) M = fmaxf(M, ml[(base + i) * 2]);
    float L = 0.f, acc = 0.f;
#pragma unroll
    for (int i = 0; i < NSPLIT; i++) {
        float w = __expf(ml[(base + i) * 2] - M);
        L   += ml[(base + i) * 2 + 1] * w;
        acc += opart[(base + i) * D_ + d] * w;
    }
    int h = kv * G_ + g;
    ctx[(size_t)b * HID_ + h * D_ + d] = acc / L;
}

// =============================================================================
// Batch GEMM v2: out[b,n] = sum_k X[b,k]*W[n,k]
//
// Layout: 128 threads = 4 warps. Warp lanes = the 32 batch rows (b = lane).
// Each warp owns 32 consecutive n (one f32x2 accumulator per n, lanes = k-pairs).
//  - x tile:  xs[k4][b] float4 -> ONE per-lane coalesced LDS.128 per k4
//  - w tile:  ws[n][k4] float4 -> uniform-address LDS.128 *broadcast* per (n,k4)
// Per k4: 33 LDS + 64 FFMA2  ->  fma-pipe bound (~1 B smem / FMA).
//
// MODE 2: plain direct write.  MODE 3: raw K-split partial.
// grid (N/128, KSPLIT). Kc = K / KSPLIT (multiple of 32).
// =============================================================================
#define GTK 32   // k-tile
template <int MODE>
__global__ __launch_bounds__(128)
void gemm_bn(const float* __restrict__ X, const float* __restrict__ W,
             float* __restrict__ out, int K, int N, int Kc) {
    __shared__ float4 ws[128 * (GTK / 4)];   // [n][k4]  128 n x 8 float4 = 16KB
    __shared__ float4 xs[(GTK / 4) * 32];    // [k4][b]   8 x 32 float4   = 4KB

    const int tid  = threadIdx.x;
    const int lane = tid & 31;           // = batch row b
    const int warp = tid >> 5;           // 0..3
    const int nb0  = warp * 32;          // warp's n base within block
    const int nblk = blockIdx.x * 128;
    const int kbeg = blockIdx.y * Kc, kend = kbeg + Kc;

    unsigned long long acc[32];
#pragma unroll
    for (int j = 0; j < 32; j++) acc[j] = 0ull;

    for (int k0 = kbeg; k0 < kend; k0 += GTK) {
        // --- load W tile: 128 n x 32 k. idx -> (n = idx>>3, k4 = idx&7)
#pragma unroll
        for (int r = 0; r < 8; r++) {
            int idx = tid + r * 128;
            int n = idx >> 3, k4 = idx & 7;
            ws[idx] = *reinterpret_cast<const float4*>(
                W + (size_t)(nblk + n) * K + k0 + k4 * 4);
        }
        // --- load X tile: 32 b x 32 k. idx -> (b = idx&31, k4 = idx>>5)
#pragma unroll
        for (int r = 0; r < 2; r++) {
            int idx = tid + r * 128;
            int bb = idx & 31, k4 = idx >> 5;
            xs[k4 * 32 + bb] = *reinterpret_cast<const float4*>(
                X + (size_t)bb * K + k0 + k4 * 4);
        }
        __syncthreads();

        const ulonglong2* wsp = reinterpret_cast<const ulonglong2*>(ws);
        const ulonglong2* xsp = reinterpret_cast<const ulonglong2*>(xs);
#pragma unroll
        for (int k4 = 0; k4 < GTK / 4; k4++) {
            ulonglong2 xv = xsp[k4 * 32 + lane];     // per-lane, coalesced
#pragma unroll
            for (int j = 0; j < 32; j++) {
                ulonglong2 wv = wsp[(nb0 + j) * (GTK / 4) + k4];  // broadcast
                ffma2(acc[j], xv.x, wv.x);
                ffma2(acc[j], xv.y, wv.y);
            }
        }
        __syncthreads();
    }

#pragma unroll
    for (int j = 0; j < 32; j++) {
        float2 f = *reinterpret_cast<float2*>(&acc[j]);
        float val = f.x + f.y;
        int n = nblk + nb0 + j;
        if (MODE == 2) {
            out[(size_t)lane * N + n] = val;
        } else {  // MODE 3: raw K-split partial
            out[((size_t)blockIdx.y * B_ + lane) * N + n] = val;
        }
    }
}

// Epilogue for K-split GEMMs: sum KS partials + bias/resid/act.
// MODE 0: +bias+resid   MODE 1: gelu(.+bias)
template <int MODE>
__global__ __launch_bounds__(256)
void epi_kernel(const float* __restrict__ part, const float* __restrict__ bias,
                const float* __restrict__ resid, float* __restrict__ out,
                int N, int KS) {
    size_t i = (size_t)blockIdx.x * 256 + threadIdx.x;
    int b = (int)(i / N);
    int n = (int)(i % N);
    float val = 0.f;
    for (int ksp = 0; ksp < KS; ksp++)
        val += part[((size_t)ksp * B_ + b) * N + n];
    if (MODE == 0) {
        val = val + bias[n] + resid[i];
    } else if (MODE == 1) {
        float v = val + bias[n];
        val = 0.5f * v * (1.0f + erff(v * 0.70710678118654752f));
    }
    out[i] = val;
}

// =============================================================================
// LayerNorm: grid B, 256 threads, row length 2048.
// =============================================================================
__global__ __launch_bounds__(256)
void ln_kernel(const float* __restrict__ in, const float* __restrict__ gg,
               const float* __restrict__ bb, float* __restrict__ out) {
    int b = blockIdx.x, tid = threadIdx.x;
    __shared__ float red[256];
    const float* row = in + (size_t)b * HID_;
    float v[8];
    float s = 0.f;
#pragma unroll
    for (int i = 0; i < 8; i++) { v[i] = row[tid + i * 256]; s += v[i]; }
    red[tid] = s; __syncthreads();
    for (int off = 128; off > 0; off >>= 1) {
        if (tid < off) red[tid] += red[tid + off];
        __syncthreads();
    }
    float mean = red[0] * (1.0f / HID_);
    __syncthreads();
    float sq = 0.f;
#pragma unroll
    for (int i = 0; i < 8; i++) { float d = v[i] - mean; sq += d * d; }
    red[tid] = sq; __syncthreads();
    for (int off = 128; off > 0; off >>= 1) {
        if (tid < off) red[tid] += red[tid + off];
        __syncthreads();
    }
    float rstd = rsqrtf(red[0] * (1.0f / HID_) + 1e-5f);
#pragma unroll
    for (int i = 0; i < 8; i++) {
        int c = tid + i * 256;
        out[(size_t)b * HID_ + c] = (v[i] - mean) * rstd * gg[c] + bb[c];
    }
}

// =============================================================================
extern "C" void kernel_launch(void* const* d_in, const int* in_sizes, int n_in,
                              void* d_out, int out_size) {
    const float* residual = (const float*)d_in[0];
    const float* q   = (const float*)d_in[1];
    const float* ks  = (const float*)d_in[2];
    const float* vs  = (const float*)d_in[3];
    const float* Wo  = (const float*)d_in[4];
    const float* bo  = (const float*)d_in[5];
    const float* g2  = (const float*)d_in[6];
    const float* b2  = (const float*)d_in[7];
    const float* W1  = (const float*)d_in[8];
    const float* b1  = (const float*)d_in[9];
    const float* W2  = (const float*)d_in[10];
    const float* b2m = (const float*)d_in[11];
    const float* gf  = (const float*)d_in[12];
    const float* bf  = (const float*)d_in[13];
    const float* Wlm = (const float*)d_in[14];
    float* out = (float*)d_out;

    float* scratch = nullptr;
    cudaGetSymbolAddress((void**)&scratch, g_scratch);
    float* ctx   = scratch + OFF_CTX;
    float* h1    = scratch + OFF_H1;
    float* x2    = scratch + OFF_X2;
    float* ff    = scratch + OFF_FF;
    float* h3    = scratch + OFF_H3;
    float* xf    = scratch + OFF_XF;
    float* opart = scratch + OFF_OPART;
    float* ml    = scratch + OFF_ML;
    float* part  = scratch + OFF_PART;

    // 1) attention
    attn_partial<<<dim3(NSPLIT, KV_, B_), 256>>>(q, ks, vs, opart, ml);
    attn_combine<<<dim3(G_, KV_, B_), 64>>>(opart, ml, ctx);

    // 2) Wo projection (+bo, +residual): 16 n-blocks x 16 K-splits = 256 blocks
    gemm_bn<3><<<dim3(HID_ / 128, 16), 128>>>(ctx, Wo, part, HID_, HID_, HID_ / 16);
    epi_kernel<0><<<(B_ * HID_) / 256, 256>>>(part, bo, residual, h1, HID_, 16);

    // 3) LN
    ln_kernel<<<B_, 256>>>(h1, g2, b2, x2);

    // 4) FFN up + GELU: 64 x 4 = 256 blocks
    gemm_bn<3><<<dim3(FF_ / 128, 4), 128>>>(x2, W1, part, HID_, FF_, HID_ / 4);
    epi_kernel<1><<<(B_ * FF_) / 256, 256>>>(part, b1, nullptr, ff, FF_, 4);

    // 5) FFN down (+b2m, +h1 residual): 16 x 16 = 256 blocks
    gemm_bn<3><<<dim3(HID_ / 128, 16), 128>>>(ff, W2, part, FF_, HID_, FF_ / 16);
    epi_kernel<0><<<(B_ * HID_) / 256, 256>>>(part, b2m, h1, h3, HID_, 16);

    // 6) final LN
    ln_kernel<<<B_, 256>>>(h3, gf, bf, xf);

    // 7) LM head -> logits: 250 blocks, one wave, direct write
    gemm_bn<2><<<dim3(V_ / 128, 1), 128>>>(xf, Wlm, out, HID_, V_, HID_);
}

// round 7
// speedup vs baseline: 1.1187x; 1.0424x over previous
#include <cuda_runtime.h>
#include <cuda_bf16.h>
#include <math.h>

// Problem constants
#define B_   32
#define H_   32
#define KV_  8
#define G_   4      // H/KV
#define S_   4096
#define D_   64
#define HID_ 2048
#define FF_  8192
#define V_   32000
#define NSPLIT 16
#define SC_  (S_/NSPLIT)   // 256

// ---------------- scratch (device global; no allocation allowed) -------------
#define OFF_CTX   0
#define OFF_H1    (OFF_CTX + B_*HID_)
#define OFF_X2    (OFF_H1 + B_*HID_)
#define OFF_FF    (OFF_X2 + B_*HID_)
#define OFF_H3    (OFF_FF + B_*FF_)
#define OFF_XF    (OFF_H3 + B_*HID_)
#define OFF_OPART (OFF_XF + B_*HID_)
#define OFF_ML    (OFF_OPART + B_*KV_*G_*NSPLIT*D_)
#define OFF_PART  (OFF_ML + B_*KV_*G_*NSPLIT*2)
#define SCRATCH_TOTAL (OFF_PART + 8*B_*FF_)   // 2M floats for K-split partials

__device__ float g_scratch[SCRATCH_TOTAL];

// packed f32x2 FMA: d(lo,hi) += a(lo,hi)*b(lo,hi). sm_103a PTX.
__device__ __forceinline__ void ffma2(unsigned long long &d,
                                      unsigned long long a,
                                      unsigned long long b) {
    asm("fma.rn.f32x2 %0, %1, %2, %0;" : "+l"(d) : "l"(a), "l"(b));
}

// cp.async helpers
__device__ __forceinline__ void cp_async16(void* smem_dst, const void* gmem_src) {
    unsigned sa = (unsigned)__cvta_generic_to_shared(smem_dst);
    asm volatile("cp.async.cg.shared.global [%0], [%1], 16;" :: "r"(sa), "l"(gmem_src));
}
__device__ __forceinline__ void cp_commit() {
    asm volatile("cp.async.commit_group;");
}
template <int N> __device__ __forceinline__ void cp_wait() {
    asm volatile("cp.async.wait_group %0;" :: "n"(N));
}

// =============================================================================
// Kernel 1: flash-decode attention partials.
// grid (NSPLIT, KV, B), 256 threads. Each block: one S-chunk of 256, G=4 heads.
// =============================================================================
__global__ __launch_bounds__(256)
void attn_partial(const float* __restrict__ q, const float* __restrict__ ks,
                  const float* __restrict__ vs,
                  float* __restrict__ opart, float* __restrict__ ml) {
    const int split = blockIdx.x, kv = blockIdx.y, b = blockIdx.z;
    const int tid = threadIdx.x;

    __shared__ float4 qs4[G_][16];
    __shared__ float  sc[G_][SC_];
    __shared__ float  red[256];
    __shared__ float  ms[G_], ls[G_];
    __shared__ float4 pc[4][G_][16];

    {
        int g = tid >> 6, kk = tid & 63;
        reinterpret_cast<float*>(qs4)[tid] =
            q[((size_t)b * H_ + kv * G_ + g) * D_ + kk];
    }
    __syncthreads();

    const int s0 = split * SC_;
    {
        const float4* kp = reinterpret_cast<const float4*>(
            ks + (((size_t)b * KV_ + kv) * S_ + s0 + tid) * D_);
        float d0 = 0.f, d1 = 0.f, d2 = 0.f, d3 = 0.f;
#pragma unroll
        for (int k4 = 0; k4 < 16; k4++) {
            float4 kvv = kp[k4];
            float4 q0 = qs4[0][k4], q1 = qs4[1][k4];
            float4 q2 = qs4[2][k4], q3 = qs4[3][k4];
            d0 += kvv.x*q0.x + kvv.y*q0.y + kvv.z*q0.z + kvv.w*q0.w;
            d1 += kvv.x*q1.x + kvv.y*q1.y + kvv.z*q1.z + kvv.w*q1.w;
            d2 += kvv.x*q2.x + kvv.y*q2.y + kvv.z*q2.z + kvv.w*q2.w;
            d3 += kvv.x*q3.x + kvv.y*q3.y + kvv.z*q3.z + kvv.w*q3.w;
        }
        const float scale = 0.125f;
        sc[0][tid] = d0 * scale; sc[1][tid] = d1 * scale;
        sc[2][tid] = d2 * scale; sc[3][tid] = d3 * scale;
    }
    __syncthreads();

    {
        int g = tid >> 6, i = tid & 63;
        float m = -1e30f;
        for (int s = i; s < SC_; s += 64) m = fmaxf(m, sc[g][s]);
        red[tid] = m; __syncthreads();
        for (int off = 32; off > 0; off >>= 1) {
            if (i < off) red[tid] = fmaxf(red[tid], red[tid + off]);
            __syncthreads();
        }
        if (i == 0) ms[g] = red[tid];
        __syncthreads();
        float mg = ms[g];
        float l = 0.f;
        for (int s = i; s < SC_; s += 64) {
            float p = __expf(sc[g][s] - mg);
            sc[g][s] = p;
            l += p;
        }
        red[tid] = l; __syncthreads();
        for (int off = 32; off > 0; off >>= 1) {
            if (i < off) red[tid] += red[tid + off];
            __syncthreads();
        }
        if (i == 0) ls[g] = red[tid];
    }
    __syncthreads();

    {
        int sg = tid >> 6, g = (tid >> 4) & 3, d4 = tid & 15;
        const float4* vp = reinterpret_cast<const float4*>(
            vs + (((size_t)b * KV_ + kv) * S_ + s0) * D_);
        float4 acc = make_float4(0.f, 0.f, 0.f, 0.f);
        for (int s = sg; s < SC_; s += 4) {
            float p = sc[g][s];
            float4 v4 = vp[s * 16 + d4];
            acc.x += p * v4.x; acc.y += p * v4.y;
            acc.z += p * v4.z; acc.w += p * v4.w;
        }
        pc[sg][g][d4] = acc;
    }
    __syncthreads();

    if (tid < 64) {
        int g = tid >> 4, d4 = tid & 15;
        float4 a = pc[0][g][d4], c1 = pc[1][g][d4];
        float4 c2 = pc[2][g][d4], c3 = pc[3][g][d4];
        float4 o;
        o.x = a.x + c1.x + c2.x + c3.x;
        o.y = a.y + c1.y + c2.y + c3.y;
        o.z = a.z + c1.z + c2.z + c3.z;
        o.w = a.w + c1.w + c2.w + c3.w;
        size_t base = ((((size_t)b * KV_ + kv) * G_ + g) * NSPLIT + split) * (size_t)D_;
        reinterpret_cast<float4*>(opart + base)[d4] = o;
    }
    if (tid < G_) {
        size_t idx = (((size_t)b * KV_ + kv) * G_ + tid) * NSPLIT + split;
        ml[idx * 2]     = ms[tid];
        ml[idx * 2 + 1] = ls[tid];
    }
}

// =============================================================================
// Kernel 2: combine split partials -> ctx [B, H*D]
// =============================================================================
__global__ __launch_bounds__(64)
void attn_combine(const float* __restrict__ opart, const float* __restrict__ ml,
                  float* __restrict__ ctx) {
    int g = blockIdx.x, kv = blockIdx.y, b = blockIdx.z, d = threadIdx.x;
    size_t base = (((size_t)b * KV_ + kv) * G_ + g) * NSPLIT;
    float M = -1e30f;
#pragma unroll
    for (int i = 0; i < NSPLIT; i++) M = fmaxf(M, ml[(base + i) * 2]);
    float L = 0.f, acc = 0.f;
#pragma unroll
    for (int i = 0; i < NSPLIT; i++) {
        float w = __expf(ml[(base + i) * 2] - M);
        L   += ml[(base + i) * 2 + 1] * w;
        acc += opart[(base + i) * D_ + d] * w;
    }
    int h = kv * G_ + g;
    ctx[(size_t)b * HID_ + h * D_ + d] = acc / L;
}

// =============================================================================
// Batch GEMM v4: out[b,n] = sum_k X[b,k]*W[n,k]
//
// 256 threads = 8 warps (2 warps/SMSP). Warp lanes = the 32 batch rows.
// BLK_N = 128: warp (w&3) owns 32 n; warps split the 32-k tile into two
// 16-k halves (kh = w>>2), combined via smem at the end.
// STATIC 40KB smem, cp.async double-buffered (no dynamic smem, no attr calls):
//   W tile 128x32 f32 = 16KB/buf, X tile 32x32 f32 = 4KB/buf.
// Per k4 per warp: 1 per-lane LDS.128 (x, conflict-free) + 32 broadcast
// LDS.128 (w) + 64 FFMA2 -> fma-pipe bound at 2 warps/SMSP.
//
// MODE 2: direct write.  MODE 3: raw K-split partial.
// grid (N/128, KSPLIT). Kc = K/KSPLIT, multiple of 32.
// =============================================================================
#define GTK 32
#define WS_F4 (128 * (GTK/4))   // 1024 float4 per buffer
#define XS_F4 (32 * (GTK/4))    // 256 float4 per buffer

template <int MODE>
__global__ __launch_bounds__(256)
void gemm_bn(const float* __restrict__ X, const float* __restrict__ W,
             float* __restrict__ out, int K, int N, int Kc) {
    __shared__ float4 ws[2 * WS_F4];   // 32KB
    __shared__ float4 xs[2 * XS_F4];   // 8KB

    const int tid  = threadIdx.x;
    const int lane = tid & 31;         // batch row b
    const int warp = tid >> 5;
    const int wq   = warp & 3;
    const int kh   = warp >> 2;        // k-half 0/1
    const int nb0  = wq * 32;
    const int nblk = blockIdx.x * 128;
    const int kbeg = blockIdx.y * Kc;
    const int ntiles = Kc / GTK;

    unsigned long long acc[32];
#pragma unroll
    for (int j = 0; j < 32; j++) acc[j] = 0ull;

    auto load_tile = [&](int t, int buf) {
        const int k0 = kbeg + t * GTK;
        float4* wd = ws + buf * WS_F4;
        float4* xd = xs + buf * XS_F4;
#pragma unroll
        for (int r = 0; r < 4; r++) {
            int idx = tid + r * 256;               // n = idx>>3, k4 = idx&7
            int n = idx >> 3, k4 = idx & 7;
            cp_async16(wd + idx,
                       W + (size_t)(nblk + n) * K + k0 + k4 * 4);
        }
        {
            int idx = tid;                         // k4 = idx>>5, b = idx&31
            int k4 = idx >> 5, bb = idx & 31;
            cp_async16(xd + idx,
                       X + (size_t)bb * K + k0 + k4 * 4);
        }
    };

    load_tile(0, 0);
    cp_commit();

    for (int t = 0; t < ntiles; t++) {
        if (t + 1 < ntiles) {
            load_tile(t + 1, (t + 1) & 1);
            cp_commit();
            cp_wait<1>();
        } else {
            cp_wait<0>();
        }
        __syncthreads();

        const ulonglong2* wsp =
            reinterpret_cast<const ulonglong2*>(ws + (t & 1) * WS_F4);
        const ulonglong2* xsp =
            reinterpret_cast<const ulonglong2*>(xs + (t & 1) * XS_F4);
#pragma unroll
        for (int kk = 0; kk < GTK / 8; kk++) {     // 4 k4 steps per warp-half
            int k4 = kh * (GTK / 8) + kk;
            ulonglong2 xv = xsp[k4 * 32 + lane];   // per-lane, conflict-free
#pragma unroll
            for (int j = 0; j < 32; j++) {
                ulonglong2 wv = wsp[(nb0 + j) * (GTK / 4) + k4];  // broadcast
                ffma2(acc[j], xv.x, wv.x);
                ffma2(acc[j], xv.y, wv.y);
            }
        }
        __syncthreads();
    }

    // combine the two k-halves via smem, then write.
    // redbuf needs 128*32 floats = 16KB; ws (32KB) is free after last sync.
    float* redbuf = reinterpret_cast<float*>(ws);
    if (kh == 1) {
#pragma unroll
        for (int j = 0; j < 32; j++) {
            float2 f = *reinterpret_cast<float2*>(&acc[j]);
            redbuf[(wq * 32 + j) * 32 + lane] = f.x + f.y;
        }
    }
    __syncthreads();
    if (kh == 0) {
#pragma unroll
        for (int j = 0; j < 32; j++) {
            float2 f = *reinterpret_cast<float2*>(&acc[j]);
            float val = (f.x + f.y) + redbuf[(wq * 32 + j) * 32 + lane];
            int n = nblk + nb0 + j;
            if (MODE == 2) {
                out[(size_t)lane * N + n] = val;
            } else {   // MODE 3: raw K-split partial
                out[((size_t)blockIdx.y * B_ + lane) * N + n] = val;
            }
        }
    }
}

// =============================================================================
// Fused epilogue + LayerNorm for HID-sized outputs.
// grid B, 256 threads. h_out = sum(part)+bias+resid ; x_out = LN(h_out)
// =============================================================================
__global__ __launch_bounds__(256)
void epi_ln(const float* __restrict__ part, const float* __restrict__ bias,
            const float* __restrict__ resid, const float* __restrict__ gg,
            const float* __restrict__ bb, float* __restrict__ h_out,
            float* __restrict__ x_out, int KS) {
    int b = blockIdx.x, tid = threadIdx.x;
    __shared__ float red[256];
    float v[8];
    float s = 0.f;
#pragma unroll
    for (int i = 0; i < 8; i++) {
        int c = tid + i * 256;
        float val = bias[c] + resid[(size_t)b * HID_ + c];
        for (int ks = 0; ks < KS; ks++)
            val += part[((size_t)ks * B_ + b) * HID_ + c];
        h_out[(size_t)b * HID_ + c] = val;
        v[i] = val; s += val;
    }
    red[tid] = s; __syncthreads();
    for (int off = 128; off > 0; off >>= 1) {
        if (tid < off) red[tid] += red[tid + off];
        __syncthreads();
    }
    float mean = red[0] * (1.0f / HID_);
    __syncthreads();
    float sq = 0.f;
#pragma unroll
    for (int i = 0; i < 8; i++) { float d = v[i] - mean; sq += d * d; }
    red[tid] = sq; __syncthreads();
    for (int off = 128; off > 0; off >>= 1) {
        if (tid < off) red[tid] += red[tid + off];
        __syncthreads();
    }
    float rstd = rsqrtf(red[0] * (1.0f / HID_) + 1e-5f);
#pragma unroll
    for (int i = 0; i < 8; i++) {
        int c = tid + i * 256;
        x_out[(size_t)b * HID_ + c] = (v[i] - mean) * rstd * gg[c] + bb[c];
    }
}

// GELU epilogue for the FFN-up K-split partials.
__global__ __launch_bounds__(256)
void epi_gelu(const float* __restrict__ part, const float* __restrict__ bias,
              float* __restrict__ out, int N, int KS) {
    size_t i = (size_t)blockIdx.x * 256 + threadIdx.x;
    int b = (int)(i / N);
    int n = (int)(i % N);
    float val = 0.f;
    for (int ks = 0; ks < KS; ks++)
        val += part[((size_t)ks * B_ + b) * N + n];
    float x = val + bias[n];
    out[i] = 0.5f * x * (1.0f + erff(x * 0.70710678118654752f));
}

// =============================================================================
extern "C" void kernel_launch(void* const* d_in, const int* in_sizes, int n_in,
                              void* d_out, int out_size) {
    const float* residual = (const float*)d_in[0];
    const float* q   = (const float*)d_in[1];
    const float* ks  = (const float*)d_in[2];
    const float* vs  = (const float*)d_in[3];
    const float* Wo  = (const float*)d_in[4];
    const float* bo  = (const float*)d_in[5];
    const float* g2  = (const float*)d_in[6];
    const float* b2  = (const float*)d_in[7];
    const float* W1  = (const float*)d_in[8];
    const float* b1  = (const float*)d_in[9];
    const float* W2  = (const float*)d_in[10];
    const float* b2m = (const float*)d_in[11];
    const float* gf  = (const float*)d_in[12];
    const float* bf  = (const float*)d_in[13];
    const float* Wlm = (const float*)d_in[14];
    float* out = (float*)d_out;

    float* scratch = nullptr;
    cudaGetSymbolAddress((void**)&scratch, g_scratch);
    float* ctx   = scratch + OFF_CTX;
    float* h1    = scratch + OFF_H1;
    float* x2    = scratch + OFF_X2;
    float* ff    = scratch + OFF_FF;
    float* h3    = scratch + OFF_H3;
    float* xf    = scratch + OFF_XF;
    float* opart = scratch + OFF_OPART;
    float* ml    = scratch + OFF_ML;
    float* part  = scratch + OFF_PART;

    // 1) attention
    attn_partial<<<dim3(NSPLIT, KV_, B_), 256>>>(q, ks, vs, opart, ml);
    attn_combine<<<dim3(G_, KV_, B_), 64>>>(opart, ml, ctx);

    // 2) Wo projection: 16 n-blocks x 16 K-splits (Kc=128, 4 tiles)
    gemm_bn<3><<<dim3(HID_ / 128, 16), 256>>>(ctx, Wo, part, HID_, HID_, HID_ / 16);
    epi_ln<<<B_, 256>>>(part, bo, residual, g2, b2, h1, x2, 16);

    // 3) FFN up: 64 n-blocks x 4 K-splits (Kc=512, 16 tiles)
    gemm_bn<3><<<dim3(FF_ / 128, 4), 256>>>(x2, W1, part, HID_, FF_, HID_ / 4);
    epi_gelu<<<(B_ * FF_) / 256, 256>>>(part, b1, ff, FF_, 4);

    // 4) FFN down: 16 n-blocks x 16 K-splits (Kc=512, 16 tiles)
    gemm_bn<3><<<dim3(HID_ / 128, 16), 256>>>(ff, W2, part, FF_, HID_, FF_ / 16);
    epi_ln<<<B_, 256>>>(part, b2m, h1, gf, bf, h3, xf, 16);

    // 5) LM head -> logits: 250 blocks, direct write
    gemm_bn<2><<<dim3(V_ / 128, 1), 256>>>(xf, Wlm, out, HID_, V_, HID_);
}

// round 8
// speedup vs baseline: 1.2734x; 1.1383x over previous
#include <cuda_runtime.h>
#include <cuda_bf16.h>
#include <math.h>

// Problem constants
#define B_   32
#define H_   32
#define KV_  8
#define G_   4      // H/KV
#define S_   4096
#define D_   64
#define HID_ 2048
#define FF_  8192
#define V_   32000
#define NSPLIT 16
#define SC_  (S_/NSPLIT)   // 256

// ---------------- scratch (device global; no allocation allowed) -------------
#define OFF_CTX   0
#define OFF_H1    (OFF_CTX + B_*HID_)
#define OFF_X2    (OFF_H1 + B_*HID_)
#define OFF_FF    (OFF_X2 + B_*HID_)
#define OFF_H3    (OFF_FF + B_*FF_)
#define OFF_XF    (OFF_H3 + B_*HID_)
#define OFF_OPART (OFF_XF + B_*HID_)
#define OFF_ML    (OFF_OPART + B_*KV_*G_*NSPLIT*D_)
#define OFF_PART  (OFF_ML + B_*KV_*G_*NSPLIT*2)
#define SCRATCH_TOTAL (OFF_PART + 16*B_*FF_)

__device__ float g_scratch[SCRATCH_TOTAL];

// packed f32x2 FMA: d(lo,hi) += a(lo,hi)*b(lo,hi). sm_103a PTX.
__device__ __forceinline__ void ffma2(unsigned long long &d,
                                      unsigned long long a,
                                      unsigned long long b) {
    asm("fma.rn.f32x2 %0, %1, %2, %0;" : "+l"(d) : "l"(a), "l"(b));
}

// cp.async helpers
__device__ __forceinline__ void cp_async16(void* smem_dst, const void* gmem_src) {
    unsigned sa = (unsigned)__cvta_generic_to_shared(smem_dst);
    asm volatile("cp.async.cg.shared.global [%0], [%1], 16;" :: "r"(sa), "l"(gmem_src));
}
__device__ __forceinline__ void cp_commit() {
    asm volatile("cp.async.commit_group;");
}
template <int N> __device__ __forceinline__ void cp_wait() {
    asm volatile("cp.async.wait_group %0;" :: "n"(N));
}

// =============================================================================
// Kernel 1: flash-decode attention partials.
// grid (NSPLIT, KV, B), 256 threads.
// =============================================================================
__global__ __launch_bounds__(256)
void attn_partial(const float* __restrict__ q, const float* __restrict__ ks,
                  const float* __restrict__ vs,
                  float* __restrict__ opart, float* __restrict__ ml) {
    const int split = blockIdx.x, kv = blockIdx.y, b = blockIdx.z;
    const int tid = threadIdx.x;

    __shared__ float4 qs4[G_][16];
    __shared__ float  sc[G_][SC_];
    __shared__ float  red[256];
    __shared__ float  ms[G_], ls[G_];
    __shared__ float4 pc[4][G_][16];

    {
        int g = tid >> 6, kk = tid & 63;
        reinterpret_cast<float*>(qs4)[tid] =
            q[((size_t)b * H_ + kv * G_ + g) * D_ + kk];
    }
    __syncthreads();

    const int s0 = split * SC_;
    {
        const float4* kp = reinterpret_cast<const float4*>(
            ks + (((size_t)b * KV_ + kv) * S_ + s0 + tid) * D_);
        float d0 = 0.f, d1 = 0.f, d2 = 0.f, d3 = 0.f;
#pragma unroll
        for (int k4 = 0; k4 < 16; k4++) {
            float4 kvv = kp[k4];
            float4 q0 = qs4[0][k4], q1 = qs4[1][k4];
            float4 q2 = qs4[2][k4], q3 = qs4[3][k4];
            d0 += kvv.x*q0.x + kvv.y*q0.y + kvv.z*q0.z + kvv.w*q0.w;
            d1 += kvv.x*q1.x + kvv.y*q1.y + kvv.z*q1.z + kvv.w*q1.w;
            d2 += kvv.x*q2.x + kvv.y*q2.y + kvv.z*q2.z + kvv.w*q2.w;
            d3 += kvv.x*q3.x + kvv.y*q3.y + kvv.z*q3.z + kvv.w*q3.w;
        }
        const float scale = 0.125f;
        sc[0][tid] = d0 * scale; sc[1][tid] = d1 * scale;
        sc[2][tid] = d2 * scale; sc[3][tid] = d3 * scale;
    }
    __syncthreads();

    {
        int g = tid >> 6, i = tid & 63;
        float m = -1e30f;
        for (int s = i; s < SC_; s += 64) m = fmaxf(m, sc[g][s]);
        red[tid] = m; __syncthreads();
        for (int off = 32; off > 0; off >>= 1) {
            if (i < off) red[tid] = fmaxf(red[tid], red[tid + off]);
            __syncthreads();
        }
        if (i == 0) ms[g] = red[tid];
        __syncthreads();
        float mg = ms[g];
        float l = 0.f;
        for (int s = i; s < SC_; s += 64) {
            float p = __expf(sc[g][s] - mg);
            sc[g][s] = p;
            l += p;
        }
        red[tid] = l; __syncthreads();
        for (int off = 32; off > 0; off >>= 1) {
            if (i < off) red[tid] += red[tid + off];
            __syncthreads();
        }
        if (i == 0) ls[g] = red[tid];
    }
    __syncthreads();

    {
        int sg = tid >> 6, g = (tid >> 4) & 3, d4 = tid & 15;
        const float4* vp = reinterpret_cast<const float4*>(
            vs + (((size_t)b * KV_ + kv) * S_ + s0) * D_);
        float4 acc = make_float4(0.f, 0.f, 0.f, 0.f);
        for (int s = sg; s < SC_; s += 4) {
            float p = sc[g][s];
            float4 v4 = vp[s * 16 + d4];
            acc.x += p * v4.x; acc.y += p * v4.y;
            acc.z += p * v4.z; acc.w += p * v4.w;
        }
        pc[sg][g][d4] = acc;
    }
    __syncthreads();

    if (tid < 64) {
        int g = tid >> 4, d4 = tid & 15;
        float4 a = pc[0][g][d4], c1 = pc[1][g][d4];
        float4 c2 = pc[2][g][d4], c3 = pc[3][g][d4];
        float4 o;
        o.x = a.x + c1.x + c2.x + c3.x;
        o.y = a.y + c1.y + c2.y + c3.y;
        o.z = a.z + c1.z + c2.z + c3.z;
        o.w = a.w + c1.w + c2.w + c3.w;
        size_t base = ((((size_t)b * KV_ + kv) * G_ + g) * NSPLIT + split) * (size_t)D_;
        reinterpret_cast<float4*>(opart + base)[d4] = o;
    }
    if (tid < G_) {
        size_t idx = (((size_t)b * KV_ + kv) * G_ + tid) * NSPLIT + split;
        ml[idx * 2]     = ms[tid];
        ml[idx * 2 + 1] = ls[tid];
    }
}

// =============================================================================
// Kernel 2: combine split partials -> ctx [B, H*D]
// =============================================================================
__global__ __launch_bounds__(64)
void attn_combine(const float* __restrict__ opart, const float* __restrict__ ml,
                  float* __restrict__ ctx) {
    int g = blockIdx.x, kv = blockIdx.y, b = blockIdx.z, d = threadIdx.x;
    size_t base = (((size_t)b * KV_ + kv) * G_ + g) * NSPLIT;
    float M = -1e30f;
#pragma unroll
    for (int i = 0; i < NSPLIT; i++) M = fmaxf(M, ml[(base + i) * 2]);
    float L = 0.f, acc = 0.f;
#pragma unroll
    for (int i = 0; i < NSPLIT; i++) {
        float w = __expf(ml[(base + i) * 2] - M);
        L   += ml[(base + i) * 2 + 1] * w;
        acc += opart[(base + i) * D_ + d] * w;
    }
    int h = kv * G_ + g;
    ctx[(size_t)b * HID_ + h * D_ + d] = acc / L;
}

// =============================================================================
// Batch GEMM v5: out[b,n] = sum_k X[b,k]*W[n,k]
//
// 256 threads = 8 warps (2/SMSP). Warp lanes = batch rows. Each warp owns
// 16 n (acc = 32 regs), all warps cover the full 32-k tile -> no combine.
// Per k4 per warp: 1 per-lane LDS.128 (x) + 16 broadcast LDS.128 (w)
// + 32 FFMA2 -> low register pressure, fma-pipe bound at 2 warps/SMSP.
// cp.async double-buffered, 40KB static smem.
// Coalesced epilogue: stage 128x32 tile in smem (pad 33), write float4 rows.
//
// MODE 2: direct write. MODE 3: K-split partial.
// grid (N/128, KSPLIT). Kc = K/KSPLIT, multiple of 32.
// =============================================================================
#define GTK 32
#define WS_F4 (128 * (GTK/4))   // 1024 float4 per buffer
#define XS_F4 (32 * (GTK/4))    // 256 float4 per buffer

template <int MODE>
__global__ __launch_bounds__(256)
void gemm_bn(const float* __restrict__ X, const float* __restrict__ W,
             float* __restrict__ out, int K, int N, int Kc) {
    __shared__ float4 ws[2 * WS_F4];   // 32KB
    __shared__ float4 xs[2 * XS_F4];   // 8KB

    const int tid  = threadIdx.x;
    const int lane = tid & 31;         // batch row b
    const int warp = tid >> 5;
    const int nb0  = warp * 16;        // warp's n base (0..112)
    const int nblk = blockIdx.x * 128;
    const int kbeg = blockIdx.y * Kc;
    const int ntiles = Kc / GTK;

    unsigned long long acc[16];
#pragma unroll
    for (int j = 0; j < 16; j++) acc[j] = 0ull;

    auto load_tile = [&](int t, int buf) {
        const int k0 = kbeg + t * GTK;
        float4* wd = ws + buf * WS_F4;
        float4* xd = xs + buf * XS_F4;
#pragma unroll
        for (int r = 0; r < 4; r++) {
            int idx = tid + r * 256;               // n = idx>>3, k4 = idx&7
            int n = idx >> 3, k4 = idx & 7;
            cp_async16(wd + idx,
                       W + (size_t)(nblk + n) * K + k0 + k4 * 4);
        }
        {
            int idx = tid;                         // k4 = idx>>5, b = idx&31
            int k4 = idx >> 5, bb = idx & 31;
            cp_async16(xd + idx,
                       X + (size_t)bb * K + k0 + k4 * 4);
        }
    };

    load_tile(0, 0);
    cp_commit();

    for (int t = 0; t < ntiles; t++) {
        if (t + 1 < ntiles) {
            load_tile(t + 1, (t + 1) & 1);
            cp_commit();
            cp_wait<1>();
        } else {
            cp_wait<0>();
        }
        __syncthreads();

        const ulonglong2* wsp =
            reinterpret_cast<const ulonglong2*>(ws + (t & 1) * WS_F4);
        const ulonglong2* xsp =
            reinterpret_cast<const ulonglong2*>(xs + (t & 1) * XS_F4);
#pragma unroll
        for (int k4 = 0; k4 < GTK / 4; k4++) {
            ulonglong2 xv = xsp[k4 * 32 + lane];   // per-lane, conflict-free
#pragma unroll
            for (int j = 0; j < 16; j++) {
                ulonglong2 wv = wsp[(nb0 + j) * (GTK / 4) + k4];  // broadcast
                ffma2(acc[j], xv.x, wv.x);
                ffma2(acc[j], xv.y, wv.y);
            }
        }
        __syncthreads();
    }

    // ---- coalesced epilogue: stage [n][b] in smem (pad to 33), write rows.
    float* redbuf = reinterpret_cast<float*>(ws);   // needs 128*33*4 = 16.9KB
#pragma unroll
    for (int j = 0; j < 16; j++) {
        float2 f = *reinterpret_cast<float2*>(&acc[j]);
        redbuf[(nb0 + j) * 33 + lane] = f.x + f.y;
    }
    __syncthreads();

    {
        int b = tid >> 3;                  // 0..31
        size_t row = (MODE == 2) ? (size_t)b
                                 : ((size_t)blockIdx.y * B_ + b);
        float* orow = out + row * N + nblk;
#pragma unroll
        for (int r = 0; r < 4; r++) {
            int n4 = (tid & 7) + r * 8;    // float4 index 0..31
            float4 v;
            v.x = redbuf[(n4 * 4 + 0) * 33 + b];
            v.y = redbuf[(n4 * 4 + 1) * 33 + b];
            v.z = redbuf[(n4 * 4 + 2) * 33 + b];
            v.w = redbuf[(n4 * 4 + 3) * 33 + b];
            *reinterpret_cast<float4*>(orow + n4 * 4) = v;
        }
    }
}

// =============================================================================
// Vectorized K-split epilogue. float4 granularity, compile-time KS + N4.
// MODE 0: +bias+resid    MODE 1: gelu(.+bias)
// grid (B*N/4/256), 256 threads.
// =============================================================================
template <int MODE, int KS, int N4>
__global__ __launch_bounds__(256)
void epi4(const float* __restrict__ part, const float* __restrict__ bias,
          const float* __restrict__ resid, float* __restrict__ out) {
    int idx = blockIdx.x * 256 + threadIdx.x;      // float4 index over B*N/4
    int b = idx / N4, n = idx % N4;
    const float4* p4 = reinterpret_cast<const float4*>(part);
    float4 v = make_float4(0.f, 0.f, 0.f, 0.f);
#pragma unroll
    for (int ks = 0; ks < KS; ks++) {
        float4 p = p4[(size_t)(ks * B_ + b) * N4 + n];
        v.x += p.x; v.y += p.y; v.z += p.z; v.w += p.w;
    }
    float4 bi = reinterpret_cast<const float4*>(bias)[n];
    if (MODE == 0) {
        float4 rs = reinterpret_cast<const float4*>(resid)[idx];
        v.x += bi.x + rs.x; v.y += bi.y + rs.y;
        v.z += bi.z + rs.z; v.w += bi.w + rs.w;
    } else {
        v.x += bi.x; v.y += bi.y; v.z += bi.z; v.w += bi.w;
        const float c = 0.70710678118654752f;
        v.x = 0.5f * v.x * (1.0f + erff(v.x * c));
        v.y = 0.5f * v.y * (1.0f + erff(v.y * c));
        v.z = 0.5f * v.z * (1.0f + erff(v.z * c));
        v.w = 0.5f * v.w * (1.0f + erff(v.w * c));
    }
    reinterpret_cast<float4*>(out)[idx] = v;
}

// =============================================================================
// LayerNorm: grid B, 256 threads, row length 2048.
// =============================================================================
__global__ __launch_bounds__(256)
void ln_kernel(const float* __restrict__ in, const float* __restrict__ gg,
               const float* __restrict__ bb, float* __restrict__ out) {
    int b = blockIdx.x, tid = threadIdx.x;
    __shared__ float red[256];
    const float* row = in + (size_t)b * HID_;
    float v[8];
    float s = 0.f;
#pragma unroll
    for (int i = 0; i < 8; i++) { v[i] = row[tid + i * 256]; s += v[i]; }
    red[tid] = s; __syncthreads();
    for (int off = 128; off > 0; off >>= 1) {
        if (tid < off) red[tid] += red[tid + off];
        __syncthreads();
    }
    float mean = red[0] * (1.0f / HID_);
    __syncthreads();
    float sq = 0.f;
#pragma unroll
    for (int i = 0; i < 8; i++) { float d = v[i] - mean; sq += d * d; }
    red[tid] = sq; __syncthreads();
    for (int off = 128; off > 0; off >>= 1) {
        if (tid < off) red[tid] += red[tid + off];
        __syncthreads();
    }
    float rstd = rsqrtf(red[0] * (1.0f / HID_) + 1e-5f);
#pragma unroll
    for (int i = 0; i < 8; i++) {
        int c = tid + i * 256;
        out[(size_t)b * HID_ + c] = (v[i] - mean) * rstd * gg[c] + bb[c];
    }
}

// =============================================================================
extern "C" void kernel_launch(void* const* d_in, const int* in_sizes, int n_in,
                              void* d_out, int out_size) {
    const float* residual = (const float*)d_in[0];
    const float* q   = (const float*)d_in[1];
    const float* ks  = (const float*)d_in[2];
    const float* vs  = (const float*)d_in[3];
    const float* Wo  = (const float*)d_in[4];
    const float* bo  = (const float*)d_in[5];
    const float* g2  = (const float*)d_in[6];
    const float* b2  = (const float*)d_in[7];
    const float* W1  = (const float*)d_in[8];
    const float* b1  = (const float*)d_in[9];
    const float* W2  = (const float*)d_in[10];
    const float* b2m = (const float*)d_in[11];
    const float* gf  = (const float*)d_in[12];
    const float* bf  = (const float*)d_in[13];
    const float* Wlm = (const float*)d_in[14];
    float* out = (float*)d_out;

    float* scratch = nullptr;
    cudaGetSymbolAddress((void**)&scratch, g_scratch);
    float* ctx   = scratch + OFF_CTX;
    float* h1    = scratch + OFF_H1;
    float* x2    = scratch + OFF_X2;
    float* ff    = scratch + OFF_FF;
    float* h3    = scratch + OFF_H3;
    float* xf    = scratch + OFF_XF;
    float* opart = scratch + OFF_OPART;
    float* ml    = scratch + OFF_ML;
    float* part  = scratch + OFF_PART;

    // 1) attention
    attn_partial<<<dim3(NSPLIT, KV_, B_), 256>>>(q, ks, vs, opart, ml);
    attn_combine<<<dim3(G_, KV_, B_), 64>>>(opart, ml, ctx);

    // 2) Wo projection: 16 n-blocks x 16 K-splits (Kc=128, 4 tiles)
    gemm_bn<3><<<dim3(HID_ / 128, 16), 256>>>(ctx, Wo, part, HID_, HID_, HID_ / 16);
    epi4<0, 16, HID_ / 4><<<(B_ * HID_) / 1024, 256>>>(part, bo, residual, h1);
    ln_kernel<<<B_, 256>>>(h1, g2, b2, x2);

    // 3) FFN up: 64 n-blocks x 4 K-splits (Kc=512, 16 tiles)
    gemm_bn<3><<<dim3(FF_ / 128, 4), 256>>>(x2, W1, part, HID_, FF_, HID_ / 4);
    epi4<1, 4, FF_ / 4><<<(B_ * FF_) / 1024, 256>>>(part, b1, nullptr, ff);

    // 4) FFN down: 16 n-blocks x 16 K-splits (Kc=512, 16 tiles)
    gemm_bn<3><<<dim3(HID_ / 128, 16), 256>>>(ff, W2, part, FF_, HID_, FF_ / 16);
    epi4<0, 16, HID_ / 4><<<(B_ * HID_) / 1024, 256>>>(part, b2m, h1, h3);
    ln_kernel<<<B_, 256>>>(h3, gf, bf, xf);

    // 5) LM head -> logits: 250 blocks, direct coalesced write
    gemm_bn<2><<<dim3(V_ / 128, 1), 256>>>(xf, Wlm, out, HID_, V_, HID_);
}

// round 11
// speedup vs baseline: 1.9272x; 1.5134x over previous
#include <cuda_runtime.h>
#include <cuda_bf16.h>
#include <math.h>

// Problem constants
#define B_   32
#define H_   32
#define KV_  8
#define G_   4      // H/KV
#define S_   4096
#define D_   64
#define HID_ 2048
#define FF_  8192
#define V_   32000
#define NSPLIT 16
#define SC_  (S_/NSPLIT)   // 256

// ---------------- scratch (device global; no allocation allowed) -------------
#define OFF_CTX   0
#define OFF_H1    (OFF_CTX + B_*HID_)
#define OFF_X2    (OFF_H1 + B_*HID_)
#define OFF_FF    (OFF_X2 + B_*HID_)
#define OFF_H3    (OFF_FF + B_*FF_)
#define OFF_XF    (OFF_H3 + B_*HID_)
#define OFF_OPART (OFF_XF + B_*HID_)
#define OFF_ML    (OFF_OPART + B_*KV_*G_*NSPLIT*D_)
#define OFF_PART  (OFF_ML + B_*KV_*G_*NSPLIT*2)
#define SCRATCH_TOTAL (OFF_PART + 16*B_*FF_)

__device__ float g_scratch[SCRATCH_TOTAL];

// =============================================================================
// warp-MMA helpers (plain sm_103-legal: HMMA via mma.sync + ldmatrix)
// =============================================================================
__device__ __forceinline__ unsigned s2u(const void* p) {
    return (unsigned)__cvta_generic_to_shared(p);
}
__device__ __forceinline__ void ldm4(unsigned* r, unsigned addr) {
    asm volatile("ldmatrix.sync.aligned.m8n8.x4.shared.b16 {%0,%1,%2,%3}, [%4];"
                 : "=r"(r[0]), "=r"(r[1]), "=r"(r[2]), "=r"(r[3]) : "r"(addr));
}
__device__ __forceinline__ void mma16816(float* d, const unsigned* a,
                                         const unsigned* b) {
    asm volatile(
        "mma.sync.aligned.m16n8k16.row.col.f32.bf16.bf16.f32 "
        "{%0,%1,%2,%3}, {%4,%5,%6,%7}, {%8,%9}, {%0,%1,%2,%3};"
        : "+f"(d[0]), "+f"(d[1]), "+f"(d[2]), "+f"(d[3])
        : "r"(a[0]), "r"(a[1]), "r"(a[2]), "r"(a[3]), "r"(b[0]), "r"(b[1]));
}

// =============================================================================
// Kernel 1: flash-decode attention partials. grid (NSPLIT, KV, B), 256 thr.
// =============================================================================
__global__ __launch_bounds__(256)
void attn_partial(const float* __restrict__ q, const float* __restrict__ ks,
                  const float* __restrict__ vs,
                  float* __restrict__ opart, float* __restrict__ ml) {
    const int split = blockIdx.x, kv = blockIdx.y, b = blockIdx.z;
    const int tid = threadIdx.x;

    __shared__ float4 qs4[G_][16];
    __shared__ float  sc[G_][SC_];
    __shared__ float  red[256];
    __shared__ float  ms[G_], ls[G_];
    __shared__ float4 pc[4][G_][16];

    {
        int g = tid >> 6, kk = tid & 63;
        reinterpret_cast<float*>(qs4)[tid] =
            q[((size_t)b * H_ + kv * G_ + g) * D_ + kk];
    }
    __syncthreads();

    const int s0 = split * SC_;
    {
        const float4* kp = reinterpret_cast<const float4*>(
            ks + (((size_t)b * KV_ + kv) * S_ + s0 + tid) * D_);
        float d0 = 0.f, d1 = 0.f, d2 = 0.f, d3 = 0.f;
#pragma unroll
        for (int k4 = 0; k4 < 16; k4++) {
            float4 kvv = kp[k4];
            float4 q0 = qs4[0][k4], q1 = qs4[1][k4];
            float4 q2 = qs4[2][k4], q3 = qs4[3][k4];
            d0 += kvv.x*q0.x + kvv.y*q0.y + kvv.z*q0.z + kvv.w*q0.w;
            d1 += kvv.x*q1.x + kvv.y*q1.y + kvv.z*q1.z + kvv.w*q1.w;
            d2 += kvv.x*q2.x + kvv.y*q2.y + kvv.z*q2.z + kvv.w*q2.w;
            d3 += kvv.x*q3.x + kvv.y*q3.y + kvv.z*q3.z + kvv.w*q3.w;
        }
        const float scale = 0.125f;
        sc[0][tid] = d0 * scale; sc[1][tid] = d1 * scale;
        sc[2][tid] = d2 * scale; sc[3][tid] = d3 * scale;
    }
    __syncthreads();

    {
        int g = tid >> 6, i = tid & 63;
        float m = -1e30f;
        for (int s = i; s < SC_; s += 64) m = fmaxf(m, sc[g][s]);
        red[tid] = m; __syncthreads();
        for (int off = 32; off > 0; off >>= 1) {
            if (i < off) red[tid] = fmaxf(red[tid], red[tid + off]);
            __syncthreads();
        }
        if (i == 0) ms[g] = red[tid];
        __syncthreads();
        float mg = ms[g];
        float l = 0.f;
        for (int s = i; s < SC_; s += 64) {
            float p = __expf(sc[g][s] - mg);
            sc[g][s] = p;
            l += p;
        }
        red[tid] = l; __syncthreads();
        for (int off = 32; off > 0; off >>= 1) {
            if (i < off) red[tid] += red[tid + off];
            __syncthreads();
        }
        if (i == 0) ls[g] = red[tid];
    }
    __syncthreads();

    {
        int sg = tid >> 6, g = (tid >> 4) & 3, d4 = tid & 15;
        const float4* vp = reinterpret_cast<const float4*>(
            vs + (((size_t)b * KV_ + kv) * S_ + s0) * D_);
        float4 acc = make_float4(0.f, 0.f, 0.f, 0.f);
        for (int s = sg; s < SC_; s += 4) {
            float p = sc[g][s];
            float4 v4 = vp[s * 16 + d4];
            acc.x += p * v4.x; acc.y += p * v4.y;
            acc.z += p * v4.z; acc.w += p * v4.w;
        }
        pc[sg][g][d4] = acc;
    }
    __syncthreads();

    if (tid < 64) {
        int g = tid >> 4, d4 = tid & 15;
        float4 a = pc[0][g][d4], c1 = pc[1][g][d4];
        float4 c2 = pc[2][g][d4], c3 = pc[3][g][d4];
        float4 o;
        o.x = a.x + c1.x + c2.x + c3.x;
        o.y = a.y + c1.y + c2.y + c3.y;
        o.z = a.z + c1.z + c2.z + c3.z;
        o.w = a.w + c1.w + c2.w + c3.w;
        size_t base = ((((size_t)b * KV_ + kv) * G_ + g) * NSPLIT + split) * (size_t)D_;
        reinterpret_cast<float4*>(opart + base)[d4] = o;
    }
    if (tid < G_) {
        size_t idx = (((size_t)b * KV_ + kv) * G_ + tid) * NSPLIT + split;
        ml[idx * 2]     = ms[tid];
        ml[idx * 2 + 1] = ls[tid];
    }
}

// =============================================================================
// Kernel 2: combine split partials -> ctx [B, H*D]
// =============================================================================
__global__ __launch_bounds__(64)
void attn_combine(const float* __restrict__ opart, const float* __restrict__ ml,
                  float* __restrict__ ctx) {
    int g = blockIdx.x, kv = blockIdx.y, b = blockIdx.z, d = threadIdx.x;
    size_t base = (((size_t)b * KV_ + kv) * G_ + g) * NSPLIT;
    float M = -1e30f;
#pragma unroll
    for (int i = 0; i < NSPLIT; i++) M = fmaxf(M, ml[(base + i) * 2]);
    float L = 0.f, acc = 0.f;
#pragma unroll
    for (int i = 0; i < NSPLIT; i++) {
        float w = __expf(ml[(base + i) * 2] - M);
        L   += ml[(base + i) * 2 + 1] * w;
        acc += opart[(base + i) * D_ + d] * w;
    }
    int h = kv * G_ + g;
    ctx[(size_t)b * HID_ + h * D_ + d] = acc / L;
}

// =============================================================================
// HMMA GEMM: out[b,n] = sum_k X[b,k]*W[n,k]
//
// D[M=128 weight rows, N=32 batch] per block. fp32 weights/acts are LDG'd to
// registers, split to bf16 hi/lo, staged in smem, consumed by
// mma.sync.m16n8k16 (bf16->f32). 3 terms: Wh*Xh + Wl*Xh + Wh*Xl.
// 8 warps: warp owns m16 rows, all 32 batch cols (4 n8 tiles).
// Smem rows padded to 40 bf16 (80B) -> conflict-free ldmatrix.
// MODE 2: direct write. MODE 3: K-split partial. grid (N/128, KSPLIT).
// =============================================================================
#define TGK 32
#define WPAD 40                       // bf16 per smem row
#define SM_WH 0                       // 128*40*2 = 10240
#define SM_WL 10240                   // 10240
#define SM_XH 20480                   // 32*40*2 = 2560
#define SM_XL 23040                   // 2560
#define SM_BYTES 25600

template <int MODE>
__global__ __launch_bounds__(256)
void gemm_mma(const float* __restrict__ X, const float* __restrict__ W,
              float* __restrict__ out, int K, int N, int Kc) {
    __shared__ char smem[SM_BYTES];

    const int tid  = threadIdx.x;
    const int warp = tid >> 5;
    const int lane = tid & 31;
    const int nblk = blockIdx.x * 128;
    const int kbeg = blockIdx.y * Kc;
    const int T    = Kc / TGK;

    float acc[4][4];
#pragma unroll
    for (int j = 0; j < 4; j++)
#pragma unroll
        for (int i = 0; i < 4; i++) acc[j][i] = 0.f;

    float4 wreg[4], xreg;

    auto load_tile = [&](int t) {
        const int k0 = kbeg + t * TGK;
#pragma unroll
        for (int r = 0; r < 4; r++) {
            int idx = tid + r * 256;            // 0..1023: row=idx>>3, f4=idx&7
            int row = idx >> 3, f4 = idx & 7;
            wreg[r] = *reinterpret_cast<const float4*>(
                W + (size_t)(nblk + row) * K + k0 + f4 * 4);
        }
        {
            int row = tid >> 3, f4 = tid & 7;   // 32 rows x 8 f4
            xreg = *reinterpret_cast<const float4*>(
                X + (size_t)row * K + k0 + f4 * 4);
        }
    };

    auto cvt_store = [&](float4 v, int row, int f4, int off_hi, int off_lo) {
        __nv_bfloat162 h01 = __float22bfloat162_rn(make_float2(v.x, v.y));
        __nv_bfloat162 h23 = __float22bfloat162_rn(make_float2(v.z, v.w));
        float lx = v.x - __bfloat162float(h01.x);
        float ly = v.y - __bfloat162float(h01.y);
        float lz = v.z - __bfloat162float(h23.x);
        float lw = v.w - __bfloat162float(h23.y);
        __nv_bfloat162 l01 = __float22bfloat162_rn(make_float2(lx, ly));
        __nv_bfloat162 l23 = __float22bfloat162_rn(make_float2(lz, lw));
        unsigned byte = (unsigned)(row * (WPAD * 2) + f4 * 8);
        *reinterpret_cast<unsigned*>(smem + off_hi + byte) =
            *reinterpret_cast<unsigned*>(&h01);
        *reinterpret_cast<unsigned*>(smem + off_hi + byte + 4) =
            *reinterpret_cast<unsigned*>(&h23);
        *reinterpret_cast<unsigned*>(smem + off_lo + byte) =
            *reinterpret_cast<unsigned*>(&l01);
        *reinterpret_cast<unsigned*>(smem + off_lo + byte + 4) =
            *reinterpret_cast<unsigned*>(&l23);
    };

    load_tile(0);

    for (int t = 0; t < T; t++) {
        // stage current regs into smem
#pragma unroll
        for (int r = 0; r < 4; r++) {
            int idx = tid + r * 256;
            cvt_store(wreg[r], idx >> 3, idx & 7, SM_WH, SM_WL);
        }
        cvt_store(xreg, tid >> 3, tid & 7, SM_XH, SM_XL);
        __syncthreads();

        if (t + 1 < T) load_tile(t + 1);   // LDG overlaps the MMAs below

        // A (W) ldmatrix addr: rows warp*16 + (lane&15), k-col (lane>>4)*8
        // B (X) ldmatrix addr: n rows (lane&7)+((lane>>4)<<3), k ((lane>>3)&1)*8
        const int arow = warp * 16 + (lane & 15);
        const int ak   = (lane >> 4) << 3;
        const int brow = (lane & 7) + ((lane >> 4) << 3);
        const int bk   = ((lane >> 3) & 1) << 3;

#pragma unroll
        for (int k16 = 0; k16 < TGK / 16; k16++) {
            const int kb = k16 * 16;   // bf16 col base
            unsigned ah[4], al[4], bh[8], bl[8];
            unsigned abyte = (unsigned)(arow * (WPAD * 2) + (kb + ak) * 2);
            ldm4(ah, s2u(smem + SM_WH) + abyte);
            ldm4(al, s2u(smem + SM_WL) + abyte);
            unsigned bbyte0 = (unsigned)(brow * (WPAD * 2) + (kb + bk) * 2);
            unsigned bbyte1 = (unsigned)((brow + 16) * (WPAD * 2) + (kb + bk) * 2);
            ldm4(bh,     s2u(smem + SM_XH) + bbyte0);
            ldm4(bh + 4, s2u(smem + SM_XH) + bbyte1);
            ldm4(bl,     s2u(smem + SM_XL) + bbyte0);
            ldm4(bl + 4, s2u(smem + SM_XL) + bbyte1);
#pragma unroll
            for (int j = 0; j < 4; j++) {
                mma16816(acc[j], ah, bh + j * 2);
                mma16816(acc[j], al, bh + j * 2);
                mma16816(acc[j], ah, bl + j * 2);
            }
        }
        __syncthreads();
    }

    // ---- stage acc -> smem [m][b] (pad 33), then coalesced write
    float* stage = reinterpret_cast<float*>(smem);   // 128*33*4 = 16896 B
    {
        int m0 = warp * 16 + (lane >> 2);
        int c0 = (lane & 3) * 2;
#pragma unroll
        for (int j = 0; j < 4; j++) {
            int c = j * 8 + c0;
            stage[m0 * 33 + c]           = acc[j][0];
            stage[m0 * 33 + c + 1]       = acc[j][1];
            stage[(m0 + 8) * 33 + c]     = acc[j][2];
            stage[(m0 + 8) * 33 + c + 1] = acc[j][3];
        }
    }
    __syncthreads();

    {
        int b = tid >> 3;
        size_t row = (MODE == 2) ? (size_t)b : ((size_t)blockIdx.y * B_ + b);
        float* orow = out + row * N + nblk;
#pragma unroll
        for (int r = 0; r < 4; r++) {
            int n4 = (tid & 7) + r * 8;
            float4 v;
            v.x = stage[(n4 * 4 + 0) * 33 + b];
            v.y = stage[(n4 * 4 + 1) * 33 + b];
            v.z = stage[(n4 * 4 + 2) * 33 + b];
            v.w = stage[(n4 * 4 + 3) * 33 + b];
            *reinterpret_cast<float4*>(orow + n4 * 4) = v;
        }
    }
}

// =============================================================================
// Vectorized K-split epilogue. MODE 0: +bias+resid  MODE 1: gelu(.+bias)
// =============================================================================
template <int MODE, int KS, int N4>
__global__ __launch_bounds__(256)
void epi4(const float* __restrict__ part, const float* __restrict__ bias,
          const float* __restrict__ resid, float* __restrict__ out) {
    int idx = blockIdx.x * 256 + threadIdx.x;
    int b = idx / N4, n = idx % N4;
    const float4* p4 = reinterpret_cast<const float4*>(part);
    float4 v = make_float4(0.f, 0.f, 0.f, 0.f);
#pragma unroll
    for (int ks = 0; ks < KS; ks++) {
        float4 p = p4[(size_t)(ks * B_ + b) * N4 + n];
        v.x += p.x; v.y += p.y; v.z += p.z; v.w += p.w;
    }
    float4 bi = reinterpret_cast<const float4*>(bias)[n];
    if (MODE == 0) {
        float4 rs = reinterpret_cast<const float4*>(resid)[idx];
        v.x += bi.x + rs.x; v.y += bi.y + rs.y;
        v.z += bi.z + rs.z; v.w += bi.w + rs.w;
    } else {
        v.x += bi.x; v.y += bi.y; v.z += bi.z; v.w += bi.w;
        const float c = 0.70710678118654752f;
        v.x = 0.5f * v.x * (1.0f + erff(v.x * c));
        v.y = 0.5f * v.y * (1.0f + erff(v.y * c));
        v.z = 0.5f * v.z * (1.0f + erff(v.z * c));
        v.w = 0.5f * v.w * (1.0f + erff(v.w * c));
    }
    reinterpret_cast<float4*>(out)[idx] = v;
}

// =============================================================================
// LayerNorm: grid B, 256 threads, row length 2048.
// =============================================================================
__global__ __launch_bounds__(256)
void ln_kernel(const float* __restrict__ in, const float* __restrict__ gg,
               const float* __restrict__ bb, float* __restrict__ out) {
    int b = blockIdx.x, tid = threadIdx.x;
    __shared__ float red[256];
    const float* row = in + (size_t)b * HID_;
    float v[8];
    float s = 0.f;
#pragma unroll
    for (int i = 0; i < 8; i++) { v[i] = row[tid + i * 256]; s += v[i]; }
    red[tid] = s; __syncthreads();
    for (int off = 128; off > 0; off >>= 1) {
        if (tid < off) red[tid] += red[tid + off];
        __syncthreads();
    }
    float mean = red[0] * (1.0f / HID_);
    __syncthreads();
    float sq = 0.f;
#pragma unroll
    for (int i = 0; i < 8; i++) { float d = v[i] - mean; sq += d * d; }
    red[tid] = sq; __syncthreads();
    for (int off = 128; off > 0; off >>= 1) {
        if (tid < off) red[tid] += red[tid + off];
        __syncthreads();
    }
    float rstd = rsqrtf(red[0] * (1.0f / HID_) + 1e-5f);
#pragma unroll
    for (int i = 0; i < 8; i++) {
        int c = tid + i * 256;
        out[(size_t)b * HID_ + c] = (v[i] - mean) * rstd * gg[c] + bb[c];
    }
}

// =============================================================================
extern "C" void kernel_launch(void* const* d_in, const int* in_sizes, int n_in,
                              void* d_out, int out_size) {
    const float* residual = (const float*)d_in[0];
    const float* q   = (const float*)d_in[1];
    const float* ks  = (const float*)d_in[2];
    const float* vs  = (const float*)d_in[3];
    const float* Wo  = (const float*)d_in[4];
    const float* bo  = (const float*)d_in[5];
    const float* g2  = (const float*)d_in[6];
    const float* b2  = (const float*)d_in[7];
    const float* W1  = (const float*)d_in[8];
    const float* b1  = (const float*)d_in[9];
    const float* W2  = (const float*)d_in[10];
    const float* b2m = (const float*)d_in[11];
    const float* gf  = (const float*)d_in[12];
    const float* bf  = (const float*)d_in[13];
    const float* Wlm = (const float*)d_in[14];
    float* out = (float*)d_out;

    float* scratch = nullptr;
    cudaGetSymbolAddress((void**)&scratch, g_scratch);
    float* ctx   = scratch + OFF_CTX;
    float* h1    = scratch + OFF_H1;
    float* x2    = scratch + OFF_X2;
    float* ff    = scratch + OFF_FF;
    float* h3    = scratch + OFF_H3;
    float* xf    = scratch + OFF_XF;
    float* opart = scratch + OFF_OPART;
    float* ml    = scratch + OFF_ML;
    float* part  = scratch + OFF_PART;

    // 1) attention
    attn_partial<<<dim3(NSPLIT, KV_, B_), 256>>>(q, ks, vs, opart, ml);
    attn_combine<<<dim3(G_, KV_, B_), 64>>>(opart, ml, ctx);

    // 2) Wo projection: 16 n-blocks x 16 K-splits (Kc=128, 4 tiles)
    gemm_mma<3><<<dim3(HID_ / 128, 16), 256>>>(ctx, Wo, part, HID_, HID_, HID_ / 16);
    epi4<0, 16, HID_ / 4><<<(B_ * HID_) / 1024, 256>>>(part, bo, residual, h1);
    ln_kernel<<<B_, 256>>>(h1, g2, b2, x2);

    // 3) FFN up: 64 n-blocks x 4 K-splits (Kc=512, 16 tiles)
    gemm_mma<3><<<dim3(FF_ / 128, 4), 256>>>(x2, W1, part, HID_, FF_, HID_ / 4);
    epi4<1, 4, FF_ / 4><<<(B_ * FF_) / 1024, 256>>>(part, b1, nullptr, ff);

    // 4) FFN down: 16 n-blocks x 16 K-splits (Kc=512, 16 tiles)
    gemm_mma<3><<<dim3(HID_ / 128, 16), 256>>>(ff, W2, part, FF_, HID_, FF_ / 16);
    epi4<0, 16, HID_ / 4><<<(B_ * HID_) / 1024, 256>>>(part, b2m, h1, h3);
    ln_kernel<<<B_, 256>>>(h3, gf, bf, xf);

    // 5) LM head -> logits: 250 blocks, K=2048 (64 tiles), direct write
    gemm_mma<2><<<dim3(V_ / 128, 1), 256>>>(xf, Wlm, out, HID_, V_, HID_);
}